// round 13
// baseline (speedup 1.0000x reference)
#include <cuda_runtime.h>
#include <cuda_fp16.h>
#include <cstdint>

// ---------------------------------------------------------------------------
//   input:  [16, 64, 128, 128]  fp32 NCHW
//   conv1:  1x1, 64 -> 256, BN+ReLU  (TF32 mma)       -> c1  NHWC fp16
//   conv2:  3x3 pad1, 256 -> 128, BN+ReLU (FP16 mma)  -> c2  NHWC fp32
//   sobel:  depthwise 3x3 pad1 (summed kernel)        -> edge NHWC fp16
//   conv3:  3x3 pad1, 128 -> 64, BN+ReLU (FP16 mma)   -> out[:,64:128] NCHW f32
//   concat: out[:,0:64] = input
//
// R8 -> R9: conv3x3 fragment loads via ldmatrix.x4 (2 for A, 4 for B per tap)
// instead of 24 scalar LDS. Same fragments, bit-identical math.
// ---------------------------------------------------------------------------

#define BATCH 16
#define HH 128
#define WWID 128
#define HWSZ (HH * WWID)
#define C_IN 64
#define C1 256
#define C2 128
#define C3 64
#define EPSV 1e-5f

__device__ __align__(16) __half g_c1h[(size_t)BATCH * HWSZ * C1];    // 128 MB
__device__ __align__(16) float g_c2f[(size_t)BATCH * HWSZ * C2];     // 128 MB
__device__ __align__(16) __half g_edgeh[(size_t)BATCH * HWSZ * C2];  // 64 MB
__device__ __align__(16) __half g_w2h[2 * 16 * 9 * 64 * 16];  // [ocb][cc][tap][oc64][ic16]
__device__ __align__(16) __half g_w3h[1 * 8 * 9 * 64 * 16];
__device__ uint32_t g_w1t[4 * 8 * 8 * 64];                    // conv1 tf32 slab

// ---------------------------------------------------------------------------
// helpers
// ---------------------------------------------------------------------------
__device__ __forceinline__ uint32_t f2tf32(float x) {
    uint32_t r;
    asm("cvt.rna.tf32.f32 %0, %1;" : "=r"(r) : "f"(x));
    return r;
}
__device__ __forceinline__ uint32_t tf32_of_bits(uint32_t b) {
    return f2tf32(__uint_as_float(b));
}

__device__ __forceinline__ void mma_tf32(float c[4], const uint32_t a[4],
                                         uint32_t b0, uint32_t b1) {
    asm volatile(
        "mma.sync.aligned.m16n8k8.row.col.f32.tf32.tf32.f32 "
        "{%0,%1,%2,%3}, {%4,%5,%6,%7}, {%8,%9}, {%0,%1,%2,%3};"
        : "+f"(c[0]), "+f"(c[1]), "+f"(c[2]), "+f"(c[3])
        : "r"(a[0]), "r"(a[1]), "r"(a[2]), "r"(a[3]), "r"(b0), "r"(b1));
}

__device__ __forceinline__ void mma_f16(float c[4], const uint32_t a[4],
                                        uint32_t b0, uint32_t b1) {
    asm volatile(
        "mma.sync.aligned.m16n8k16.row.col.f32.f16.f16.f32 "
        "{%0,%1,%2,%3}, {%4,%5,%6,%7}, {%8,%9}, {%0,%1,%2,%3};"
        : "+f"(c[0]), "+f"(c[1]), "+f"(c[2]), "+f"(c[3])
        : "r"(a[0]), "r"(a[1]), "r"(a[2]), "r"(a[3]), "r"(b0), "r"(b1));
}

__device__ __forceinline__ void ldsm_x4(uint32_t r[4], uint32_t addr) {
    asm volatile(
        "ldmatrix.sync.aligned.m8n8.x4.shared.b16 {%0,%1,%2,%3}, [%4];"
        : "=r"(r[0]), "=r"(r[1]), "=r"(r[2]), "=r"(r[3])
        : "r"(addr));
}

__device__ __forceinline__ void cp_async16(uint32_t dst, const void* src) {
    asm volatile("cp.async.cg.shared.global [%0], [%1], 16;\n" ::"r"(dst),
                 "l"(src));
}
__device__ __forceinline__ void cp_commit() {
    asm volatile("cp.async.commit_group;\n" ::: "memory");
}
__device__ __forceinline__ void cp_wait1() {
    asm volatile("cp.async.wait_group 1;\n" ::: "memory");
}
__device__ __forceinline__ void cp_wait0() {
    asm volatile("cp.async.wait_group 0;\n" ::: "memory");
}

// ---------------------------------------------------------------------------
// weight prep
// ---------------------------------------------------------------------------
__global__ void prep_w3x3_h(const float* __restrict__ w,
                            __half* __restrict__ o, int OC, int CIN) {
    int t = blockIdx.x * 256 + threadIdx.x;
    int total = OC * CIN * 9;
    if (t >= total) return;
    int oc = t / (CIN * 9);
    int r = t - oc * (CIN * 9);
    int ic = r / 9;
    int tap = r - ic * 9;
    int ocb = oc >> 6, oc64 = oc & 63;
    int cc = ic >> 4, icr = ic & 15;
    int NC = CIN / 16;
    o[((((size_t)ocb * NC + cc) * 9 + tap) * 64 + oc64) * 16 + icr] =
        __float2half(w[t]);
}

__global__ void prep_w1x1(const float* __restrict__ w,
                          uint32_t* __restrict__ o) {
    int t = blockIdx.x * 256 + threadIdx.x;
    if (t >= C1 * C_IN) return;
    int oc = t / C_IN;
    int ic = t - oc * C_IN;
    int ocb = oc >> 6, oc64 = oc & 63;
    int cc = ic >> 3, icr = ic & 7;
    o[(((size_t)ocb * 8 + cc) * 8 + icr) * 64 + oc64] = f2tf32(w[t]);
}

// ---------------------------------------------------------------------------
// conv1: 1x1 64->256, TF32 mma, cp.async pipelined -> NHWC fp16
// ---------------------------------------------------------------------------
#define X1_BUF_W 2112  // 8*264
#define W1_BUF_W 576   // 8*72
#define SMEM1X1_BYTES ((2 * X1_BUF_W + 2 * W1_BUF_W) * 4)

__global__ __launch_bounds__(256, 2) void conv1x1_mma_pipe(
    const float* __restrict__ x, const uint32_t* __restrict__ wslab,
    const float* __restrict__ bb, const float* __restrict__ gg,
    const float* __restrict__ be, const float* __restrict__ mm,
    const float* __restrict__ vv, __half* __restrict__ out) {
    constexpr int NC = 8;
    extern __shared__ uint32_t dsm[];
    uint32_t* Xb[2] = {dsm, dsm + X1_BUF_W};
    uint32_t* Wb[2] = {dsm + 2 * X1_BUF_W, dsm + 2 * X1_BUF_W + W1_BUF_W};
    const uint32_t smem_u32 = (uint32_t)__cvta_generic_to_shared((void*)dsm);

    const int pxBase = blockIdx.x * 256;
    const int ocb = blockIdx.y;
    const int b = blockIdx.z;
    const int tid = threadIdx.x;
    const int lane = tid & 31;
    const int warp = tid >> 5;

    const int wm = warp >> 2;
    const int wn = warp & 3;
    const int px0 = wn * 64;
    const int tig = lane & 3;
    const int grp = lane >> 2;

    const float* xb = x + (size_t)b * C_IN * HWSZ + pxBase;
    const uint32_t* ws_base = wslab + (size_t)ocb * NC * (8 * 64);

    float acc[2][8][4];
    #pragma unroll
    for (int mf = 0; mf < 2; mf++)
        #pragma unroll
        for (int nf = 0; nf < 8; nf++)
            #pragma unroll
            for (int r = 0; r < 4; r++) acc[mf][nf][r] = 0.f;

    auto stage = [&](int buf, int cc) {
        const uint32_t xdst0 = smem_u32 + (buf ? X1_BUF_W * 4 : 0);
        const float* src = xb + (size_t)(cc * 8) * HWSZ;
        #pragma unroll
        for (int i = tid; i < 8 * 64; i += 256) {
            int ic = i >> 6;
            int piece = i & 63;
            cp_async16(xdst0 + (ic * 264 + piece * 4) * 4,
                       src + (size_t)ic * HWSZ + piece * 4);
        }
        const uint32_t wdst0 =
            smem_u32 + (2 * X1_BUF_W + (buf ? W1_BUF_W : 0)) * 4;
        const uint32_t* ws = ws_base + (size_t)cc * (8 * 64);
        if (tid < 128) {
            int row = tid >> 4;
            int piece = tid & 15;
            cp_async16(wdst0 + (row * 72 + piece * 4) * 4,
                       ws + row * 64 + piece * 4);
        }
    };

    auto compute = [&](int buf) {
        const uint32_t* pB = Xb[buf] + tig * 264 + px0 + grp;
        const uint32_t* pA = Wb[buf] + tig * 72 + wm * 32 + grp;
        uint32_t a[2][4];
        #pragma unroll
        for (int mf = 0; mf < 2; mf++) {
            const int base = mf * 16;
            a[mf][0] = pA[base];
            a[mf][1] = pA[base + 8];
            a[mf][2] = pA[base + 288];
            a[mf][3] = pA[base + 296];
        }
        #pragma unroll
        for (int nf = 0; nf < 8; nf++) {
            uint32_t b0 = tf32_of_bits(pB[nf * 8]);
            uint32_t b1 = tf32_of_bits(pB[1056 + nf * 8]);
            mma_tf32(acc[0][nf], a[0], b0, b1);
            mma_tf32(acc[1][nf], a[1], b0, b1);
        }
    };

    stage(0, 0);
    cp_commit();
    int buf = 0;
    for (int cc = 0; cc < NC; ++cc) {
        if (cc + 1 < NC) stage(buf ^ 1, cc + 1);
        cp_commit();
        if (cc + 1 < NC) cp_wait1(); else cp_wait0();
        __syncthreads();
        compute(buf);
        __syncthreads();
        buf ^= 1;
    }

    // epilogue: BN + ReLU -> NHWC fp16
    #pragma unroll
    for (int mf = 0; mf < 2; mf++) {
        #pragma unroll
        for (int rr = 0; rr < 2; rr++) {
            int oc = ocb * 64 + wm * 32 + mf * 16 + grp + rr * 8;
            float s = __ldg(&gg[oc]) * rsqrtf(__ldg(&vv[oc]) + EPSV);
            float t = (__ldg(&bb[oc]) - __ldg(&mm[oc])) * s + __ldg(&be[oc]);
            #pragma unroll
            for (int nf = 0; nf < 8; nf++) {
                float v0 = fmaxf(fmaf(acc[mf][nf][rr * 2 + 0], s, t), 0.f);
                float v1 = fmaxf(fmaf(acc[mf][nf][rr * 2 + 1], s, t), 0.f);
                int pxl = pxBase + px0 + nf * 8 + tig * 2;
                __half* dst = out + ((size_t)b * HWSZ + pxl) * C1 + oc;
                dst[0] = __float2half(v0);
                dst[C1] = __float2half(v1);
            }
        }
    }
}

// ---------------------------------------------------------------------------
// conv3x3 fp16 implicit GEMM, ldmatrix fragment loads.
// CTA: 256 px (2 output rows) x 64 oc. 8 warps: warp = m32 x n64.
// X smem: [4 rows][130 px][12 words]; W smem: [9 tap][64 oc][12 words].
// Row stride 48B -> ldmatrix phases hit all 32 banks (12k mod 32 distinct).
// MODE 0: out NHWC fp32 (C=128).  MODE 1: out NCHW fp32, ch offset 64.
// ---------------------------------------------------------------------------
#define XPXW 12
#define XROWW (130 * XPXW)
#define XBUFW (4 * XROWW)          // 6240
#define WBUFW (576 * XPXW)         // 6912
#define SMEMF16_WORDS (2 * XBUFW + 2 * WBUFW)
#define SMEMF16_BYTES (SMEMF16_WORDS * 4)

template <int CIN, int MODE>
__global__ __launch_bounds__(256, 2) void conv3x3_f16(
    const __half* __restrict__ in, const __half* __restrict__ wslab,
    const float* __restrict__ bb, const float* __restrict__ gg,
    const float* __restrict__ be, const float* __restrict__ mm,
    const float* __restrict__ vv, float* __restrict__ outp) {
    constexpr int NC = CIN / 16;
    extern __shared__ uint32_t dsm[];
    const uint32_t smem_u32 = (uint32_t)__cvta_generic_to_shared((void*)dsm);

    const int y0 = blockIdx.x * 2;
    const int ocb = blockIdx.y;
    const int b = blockIdx.z;
    const int tid = threadIdx.x;
    const int lane = tid & 31;
    const int warp = tid >> 5;
    const int row_out = warp >> 2;
    const int x0 = (warp & 3) * 32;
    const int grp = lane >> 2;
    const int tig = lane & 3;

    const __half* inb = in + (size_t)b * HWSZ * CIN;
    const __half* wsb = wslab + (size_t)ocb * ((size_t)NC * 9 * 64 * 16);

    // zero X halo regions once, then barrier before any cp.async can land
    for (int i = tid; i < 2 * XBUFW; i += 256) dsm[i] = 0;
    __syncthreads();

    float acc[2][8][4];
    #pragma unroll
    for (int mf = 0; mf < 2; mf++)
        #pragma unroll
        for (int nf = 0; nf < 8; nf++)
            #pragma unroll
            for (int r = 0; r < 4; r++) acc[mf][nf][r] = 0.f;

    // ---- per-lane ldmatrix base addresses (byte offsets, buf-relative) ----
    const int lg = lane >> 3;   // lane group 0..3 -> x4 tile slot
    const int r8 = lane & 7;
    // A tiles: reg0 rows+0 k-lo | reg1 rows+8 k-lo | reg2 rows+0 k-hi | reg3 rows+8 k-hi
    const int mA = ((lg & 1) << 3) + r8;
    const int pieceA = lg >> 1;
    uint32_t aRel[2];
    #pragma unroll
    for (int mf = 0; mf < 2; mf++)
        aRel[mf] = ((row_out * 130 + x0 + mf * 16 + mA) * XPXW + pieceA * 4) * 4;
    // B tiles: reg0 oc+0 k-lo | reg1 oc+0 k-hi | reg2 oc+8 k-lo | reg3 oc+8 k-hi
    const int ocB = ((lg >> 1) << 3) + r8;
    const int pieceB = lg & 1;
    uint32_t bRel[4];
    #pragma unroll
    for (int p = 0; p < 4; p++)
        bRel[p] = ((p * 16 + ocB) * XPXW + pieceB * 4) * 4;

    auto stage = [&](int buf, int cc) {
        const uint32_t xdst = smem_u32 + (buf ? XBUFW * 4 : 0);
        const __half* xs = inb + cc * 16;
        #pragma unroll
        for (int i = tid; i < 1024; i += 256) {
            int row = i >> 8;
            int r = i & 255;
            int px = r >> 1;
            int piece = r & 1;
            int gy = y0 - 1 + row;
            if ((unsigned)gy < (unsigned)HH)
                cp_async16(xdst + (((row * 130) + px + 1) * XPXW + piece * 4) * 4,
                           xs + ((size_t)gy * WWID + px) * CIN + piece * 8);
        }
        const uint32_t wdst = smem_u32 + (2 * XBUFW + (buf ? WBUFW : 0)) * 4;
        const __half* ws = wsb + (size_t)cc * (9 * 64 * 16);
        #pragma unroll
        for (int i = tid; i < 1152; i += 256) {
            int row = i >> 1;
            int piece = i & 1;
            cp_async16(wdst + (row * XPXW + piece * 4) * 4,
                       ws + row * 16 + piece * 8);
        }
    };

    auto compute = [&](int buf) {
        const uint32_t xo = smem_u32 + (buf ? XBUFW * 4u : 0u);
        const uint32_t wo = smem_u32 + (2 * XBUFW + (buf ? WBUFW : 0)) * 4u;
        #pragma unroll
        for (int tap = 0; tap < 9; ++tap) {
            const int ky = tap / 3;
            const int kx = tap - ky * 3;
            const uint32_t tA = (uint32_t)((ky * 130 + kx) * XPXW * 4);
            uint32_t a[2][4];
            ldsm_x4(a[0], xo + aRel[0] + tA);
            ldsm_x4(a[1], xo + aRel[1] + tA);
            const uint32_t tB = wo + (uint32_t)(tap * 64 * XPXW * 4);
            #pragma unroll
            for (int p = 0; p < 4; p++) {
                uint32_t bf[4];
                ldsm_x4(bf, tB + bRel[p]);
                mma_f16(acc[0][2 * p], a[0], bf[0], bf[1]);
                mma_f16(acc[1][2 * p], a[1], bf[0], bf[1]);
                mma_f16(acc[0][2 * p + 1], a[0], bf[2], bf[3]);
                mma_f16(acc[1][2 * p + 1], a[1], bf[2], bf[3]);
            }
        }
    };

    stage(0, 0);
    cp_commit();
    int buf = 0;
    for (int cc = 0; cc < NC; ++cc) {
        if (cc + 1 < NC) stage(buf ^ 1, cc + 1);
        cp_commit();
        if (cc + 1 < NC) cp_wait1(); else cp_wait0();
        __syncthreads();
        compute(buf);
        __syncthreads();
        buf ^= 1;
    }

    if (MODE == 0) {
        // NHWC fp32 output (c2 stays full precision for sobel cancellation)
        float* out = outp + (size_t)b * HWSZ * C2;
        #pragma unroll
        for (int nf = 0; nf < 8; nf++) {
            int oc = ocb * 64 + nf * 8 + 2 * tig;
            float s0 = __ldg(&gg[oc]) * rsqrtf(__ldg(&vv[oc]) + EPSV);
            float t0 = (__ldg(&bb[oc]) - __ldg(&mm[oc])) * s0 + __ldg(&be[oc]);
            float s1 = __ldg(&gg[oc + 1]) * rsqrtf(__ldg(&vv[oc + 1]) + EPSV);
            float t1 = (__ldg(&bb[oc + 1]) - __ldg(&mm[oc + 1])) * s1 +
                       __ldg(&be[oc + 1]);
            #pragma unroll
            for (int mf = 0; mf < 2; mf++)
                #pragma unroll
                for (int h = 0; h < 2; h++) {
                    int px = (y0 + row_out) * WWID + x0 + mf * 16 + grp + h * 8;
                    float2 v;
                    v.x = fmaxf(fmaf(acc[mf][nf][h * 2 + 0], s0, t0), 0.f);
                    v.y = fmaxf(fmaf(acc[mf][nf][h * 2 + 1], s1, t1), 0.f);
                    *(float2*)(out + (size_t)px * C2 + oc) = v;
                }
        }
    } else {
        // NCHW fp32 output at channel offset 64, smem transpose for coalescing
        float* Csm = (float*)dsm;  // [256 px][stride 65]
        #pragma unroll
        for (int nf = 0; nf < 8; nf++) {
            int ocL = nf * 8 + 2 * tig;
            float s0 = __ldg(&gg[ocL]) * rsqrtf(__ldg(&vv[ocL]) + EPSV);
            float t0 =
                (__ldg(&bb[ocL]) - __ldg(&mm[ocL])) * s0 + __ldg(&be[ocL]);
            float s1 = __ldg(&gg[ocL + 1]) * rsqrtf(__ldg(&vv[ocL + 1]) + EPSV);
            float t1 = (__ldg(&bb[ocL + 1]) - __ldg(&mm[ocL + 1])) * s1 +
                       __ldg(&be[ocL + 1]);
            #pragma unroll
            for (int mf = 0; mf < 2; mf++)
                #pragma unroll
                for (int h = 0; h < 2; h++) {
                    int pxL = row_out * 128 + x0 + mf * 16 + grp + h * 8;
                    Csm[pxL * 65 + ocL] =
                        fmaxf(fmaf(acc[mf][nf][h * 2 + 0], s0, t0), 0.f);
                    Csm[pxL * 65 + ocL + 1] =
                        fmaxf(fmaf(acc[mf][nf][h * 2 + 1], s1, t1), 0.f);
                }
        }
        __syncthreads();
        #pragma unroll
        for (int i = 0; i < 8; i++) {
            int ocL = warp * 8 + i;
            float* op =
                outp + ((size_t)(b * 128 + 64 + ocL)) * HWSZ + y0 * WWID;
            #pragma unroll
            for (int c = 0; c < 8; c++) {
                int pxL = c * 32 + lane;
                op[pxL] = Csm[pxL * 65 + ocL];
            }
        }
    }
}

// ---------------------------------------------------------------------------
// sobel depthwise: NHWC fp32 in -> NHWC fp16 out (8 channels / thread)
// kernel (correlation): [[2,4,4],[-2,0,2],[-4,-4,-2]]
// ---------------------------------------------------------------------------
__global__ __launch_bounds__(256) void sobel_nhwc(const float* __restrict__ in,
                                                  __half* __restrict__ out) {
    int idx = blockIdx.x * 256 + threadIdx.x;  // B*HW*16 threads
    int cg = idx & 15;
    int x = (idx >> 4) & 127;
    int y = (idx >> 11) & 127;
    int b = idx >> 18;
    const float* base = in + ((size_t)b * HWSZ + y * WWID + x) * C2 + cg * 8;

    float acc[8];
    #pragma unroll
    for (int k = 0; k < 8; k++) acc[k] = 0.f;

    auto add = [&](int dy, int dx, float c) {
        int yy = y + dy, xx = x + dx;
        if ((unsigned)yy < (unsigned)HH && (unsigned)xx < (unsigned)WWID) {
            const float* p = base + (dy * WWID + dx) * C2;
            float4 v0 = *(const float4*)p;
            float4 v1 = *(const float4*)(p + 4);
            acc[0] = fmaf(c, v0.x, acc[0]);
            acc[1] = fmaf(c, v0.y, acc[1]);
            acc[2] = fmaf(c, v0.z, acc[2]);
            acc[3] = fmaf(c, v0.w, acc[3]);
            acc[4] = fmaf(c, v1.x, acc[4]);
            acc[5] = fmaf(c, v1.y, acc[5]);
            acc[6] = fmaf(c, v1.z, acc[6]);
            acc[7] = fmaf(c, v1.w, acc[7]);
        }
    };
    add(-1, -1, 2.f);  add(-1, 0, 4.f);  add(-1, 1, 4.f);
    add(0, -1, -2.f);                    add(0, 1, 2.f);
    add(1, -1, -4.f);  add(1, 0, -4.f);  add(1, 1, -2.f);

    __half2 r[4];
    #pragma unroll
    for (int k = 0; k < 4; k++)
        r[k] = __floats2half2_rn(acc[2 * k], acc[2 * k + 1]);
    *(uint4*)(out + ((size_t)b * HWSZ + y * WWID + x) * C2 + cg * 8) =
        *(uint4*)r;
}

// ---------------------------------------------------------------------------
__global__ __launch_bounds__(256) void concat_copy(const float4* __restrict__ in,
                                                   float4* __restrict__ out) {
    int idx = blockIdx.x * 256 + threadIdx.x;
    int b = idx >> 18;
    int r = idx & 262143;
    out[(size_t)b * 524288 + r] = in[(size_t)b * 262144 + r];
}

// ---------------------------------------------------------------------------
extern "C" void kernel_launch(void* const* d_in, const int* in_sizes, int n_in,
                              void* d_out, int out_size) {
    const float* input = (const float*)d_in[0];
    const float* w1 = (const float*)d_in[1];
    const float* b1 = (const float*)d_in[2];
    const float* g1 = (const float*)d_in[3];
    const float* be1 = (const float*)d_in[4];
    const float* m1 = (const float*)d_in[5];
    const float* v1 = (const float*)d_in[6];
    const float* w2 = (const float*)d_in[7];
    const float* b2 = (const float*)d_in[8];
    const float* g2 = (const float*)d_in[9];
    const float* be2 = (const float*)d_in[10];
    const float* m2 = (const float*)d_in[11];
    const float* v2 = (const float*)d_in[12];
    const float* w3 = (const float*)d_in[13];
    const float* b3 = (const float*)d_in[14];
    const float* g3 = (const float*)d_in[15];
    const float* be3 = (const float*)d_in[16];
    const float* m3 = (const float*)d_in[17];
    const float* v3 = (const float*)d_in[18];
    float* out = (float*)d_out;

    __half *c1h, *edgeh, *w2h, *w3h;
    float* c2f;
    uint32_t* w1t;
    cudaGetSymbolAddress((void**)&c1h, g_c1h);
    cudaGetSymbolAddress((void**)&c2f, g_c2f);
    cudaGetSymbolAddress((void**)&edgeh, g_edgeh);
    cudaGetSymbolAddress((void**)&w2h, g_w2h);
    cudaGetSymbolAddress((void**)&w3h, g_w3h);
    cudaGetSymbolAddress((void**)&w1t, g_w1t);

    static int attr_done = 0;
    if (!attr_done) {
        cudaFuncSetAttribute(conv1x1_mma_pipe,
                             cudaFuncAttributeMaxDynamicSharedMemorySize,
                             SMEM1X1_BYTES);
        cudaFuncSetAttribute(conv3x3_f16<C1, 0>,
                             cudaFuncAttributeMaxDynamicSharedMemorySize,
                             SMEMF16_BYTES);
        cudaFuncSetAttribute(conv3x3_f16<C2, 1>,
                             cudaFuncAttributeMaxDynamicSharedMemorySize,
                             SMEMF16_BYTES);
        attr_done = 1;
    }

    // weight prep
    prep_w1x1<<<(C1 * C_IN + 255) / 256, 256>>>(w1, w1t);
    prep_w3x3_h<<<(C2 * C1 * 9 + 255) / 256, 256>>>(w2, w2h, C2, C1);
    prep_w3x3_h<<<(C3 * C2 * 9 + 255) / 256, 256>>>(w3, w3h, C3, C2);

    // conv1: 1x1 64->256 (TF32) -> NHWC fp16
    conv1x1_mma_pipe<<<dim3(HWSZ / 256, C1 / 64, BATCH), 256, SMEM1X1_BYTES>>>(
        input, w1t, b1, g1, be1, m1, v1, c1h);

    // conv2: 3x3 256->128 (FP16 mma, ldmatrix) -> NHWC fp32
    conv3x3_f16<C1, 0><<<dim3(HH / 2, 2, BATCH), 256, SMEMF16_BYTES>>>(
        c1h, w2h, b2, g2, be2, m2, v2, c2f);

    // sobel depthwise (fp32 in -> fp16 out)
    sobel_nhwc<<<BATCH * HWSZ * (C2 / 8) / 256, 256>>>(c2f, edgeh);

    // conv3: 3x3 128->64 (FP16 mma, ldmatrix) -> out[:,64:128] NCHW fp32
    conv3x3_f16<C2, 1><<<dim3(HH / 2, 1, BATCH), 256, SMEMF16_BYTES>>>(
        edgeh, w3h, b3, g3, be3, m3, v3, out);

    // concat: out[:,0:64] = input
    concat_copy<<<BATCH * (C_IN * HWSZ / 4) / 256, 256>>>(
        (const float4*)input, (float4*)out);
}

// round 14
// speedup vs baseline: 1.0024x; 1.0024x over previous
#include <cuda_runtime.h>
#include <cuda_fp16.h>
#include <cstdint>

// ---------------------------------------------------------------------------
//   input:  [16, 64, 128, 128]  fp32 NCHW
//   conv1:  1x1, 64 -> 256, BN+ReLU  (TF32 mma)       -> c1  NHWC fp16
//   conv2:  3x3 pad1, 256 -> 128, BN+ReLU (FP16 mma)  -> c2  NHWC fp32
//   sobel:  depthwise 3x3 pad1 (summed kernel)        -> edge NHWC fp16
//   conv3:  3x3 pad1, 128 -> 64, BN+ReLU (FP16 mma)   -> out[:,64:128] NCHW f32
//   concat: out[:,0:64] = input
//
// R8 -> R9: conv3x3 fragment loads via ldmatrix.x4 (2 for A, 4 for B per tap)
// instead of 24 scalar LDS. Same fragments, bit-identical math.
// ---------------------------------------------------------------------------

#define BATCH 16
#define HH 128
#define WWID 128
#define HWSZ (HH * WWID)
#define C_IN 64
#define C1 256
#define C2 128
#define C3 64
#define EPSV 1e-5f

__device__ __align__(16) __half g_c1h[(size_t)BATCH * HWSZ * C1];    // 128 MB
__device__ __align__(16) float g_c2f[(size_t)BATCH * HWSZ * C2];     // 128 MB
__device__ __align__(16) __half g_edgeh[(size_t)BATCH * HWSZ * C2];  // 64 MB
__device__ __align__(16) __half g_w2h[2 * 16 * 9 * 64 * 16];  // [ocb][cc][tap][oc64][ic16]
__device__ __align__(16) __half g_w3h[1 * 8 * 9 * 64 * 16];
__device__ uint32_t g_w1t[4 * 8 * 8 * 64];                    // conv1 tf32 slab

// ---------------------------------------------------------------------------
// helpers
// ---------------------------------------------------------------------------
__device__ __forceinline__ uint32_t f2tf32(float x) {
    uint32_t r;
    asm("cvt.rna.tf32.f32 %0, %1;" : "=r"(r) : "f"(x));
    return r;
}
__device__ __forceinline__ uint32_t tf32_of_bits(uint32_t b) {
    return f2tf32(__uint_as_float(b));
}

__device__ __forceinline__ void mma_tf32(float c[4], const uint32_t a[4],
                                         uint32_t b0, uint32_t b1) {
    asm volatile(
        "mma.sync.aligned.m16n8k8.row.col.f32.tf32.tf32.f32 "
        "{%0,%1,%2,%3}, {%4,%5,%6,%7}, {%8,%9}, {%0,%1,%2,%3};"
        : "+f"(c[0]), "+f"(c[1]), "+f"(c[2]), "+f"(c[3])
        : "r"(a[0]), "r"(a[1]), "r"(a[2]), "r"(a[3]), "r"(b0), "r"(b1));
}

__device__ __forceinline__ void mma_f16(float c[4], const uint32_t a[4],
                                        uint32_t b0, uint32_t b1) {
    asm volatile(
        "mma.sync.aligned.m16n8k16.row.col.f32.f16.f16.f32 "
        "{%0,%1,%2,%3}, {%4,%5,%6,%7}, {%8,%9}, {%0,%1,%2,%3};"
        : "+f"(c[0]), "+f"(c[1]), "+f"(c[2]), "+f"(c[3])
        : "r"(a[0]), "r"(a[1]), "r"(a[2]), "r"(a[3]), "r"(b0), "r"(b1));
}

__device__ __forceinline__ void ldsm_x4(uint32_t r[4], uint32_t addr) {
    asm volatile(
        "ldmatrix.sync.aligned.m8n8.x4.shared.b16 {%0,%1,%2,%3}, [%4];"
        : "=r"(r[0]), "=r"(r[1]), "=r"(r[2]), "=r"(r[3])
        : "r"(addr));
}

__device__ __forceinline__ void cp_async16(uint32_t dst, const void* src) {
    asm volatile("cp.async.cg.shared.global [%0], [%1], 16;\n" ::"r"(dst),
                 "l"(src));
}
__device__ __forceinline__ void cp_commit() {
    asm volatile("cp.async.commit_group;\n" ::: "memory");
}
__device__ __forceinline__ void cp_wait1() {
    asm volatile("cp.async.wait_group 1;\n" ::: "memory");
}
__device__ __forceinline__ void cp_wait0() {
    asm volatile("cp.async.wait_group 0;\n" ::: "memory");
}

// ---------------------------------------------------------------------------
// weight prep
// ---------------------------------------------------------------------------
__global__ void prep_w3x3_h(const float* __restrict__ w,
                            __half* __restrict__ o, int OC, int CIN) {
    int t = blockIdx.x * 256 + threadIdx.x;
    int total = OC * CIN * 9;
    if (t >= total) return;
    int oc = t / (CIN * 9);
    int r = t - oc * (CIN * 9);
    int ic = r / 9;
    int tap = r - ic * 9;
    int ocb = oc >> 6, oc64 = oc & 63;
    int cc = ic >> 4, icr = ic & 15;
    int NC = CIN / 16;
    o[((((size_t)ocb * NC + cc) * 9 + tap) * 64 + oc64) * 16 + icr] =
        __float2half(w[t]);
}

__global__ void prep_w1x1(const float* __restrict__ w,
                          uint32_t* __restrict__ o) {
    int t = blockIdx.x * 256 + threadIdx.x;
    if (t >= C1 * C_IN) return;
    int oc = t / C_IN;
    int ic = t - oc * C_IN;
    int ocb = oc >> 6, oc64 = oc & 63;
    int cc = ic >> 3, icr = ic & 7;
    o[(((size_t)ocb * 8 + cc) * 8 + icr) * 64 + oc64] = f2tf32(w[t]);
}

// ---------------------------------------------------------------------------
// conv1: 1x1 64->256, TF32 mma, cp.async pipelined -> NHWC fp16
// ---------------------------------------------------------------------------
#define X1_BUF_W 2112  // 8*264
#define W1_BUF_W 576   // 8*72
#define SMEM1X1_BYTES ((2 * X1_BUF_W + 2 * W1_BUF_W) * 4)

__global__ __launch_bounds__(256, 2) void conv1x1_mma_pipe(
    const float* __restrict__ x, const uint32_t* __restrict__ wslab,
    const float* __restrict__ bb, const float* __restrict__ gg,
    const float* __restrict__ be, const float* __restrict__ mm,
    const float* __restrict__ vv, __half* __restrict__ out) {
    constexpr int NC = 8;
    extern __shared__ uint32_t dsm[];
    uint32_t* Xb[2] = {dsm, dsm + X1_BUF_W};
    uint32_t* Wb[2] = {dsm + 2 * X1_BUF_W, dsm + 2 * X1_BUF_W + W1_BUF_W};
    const uint32_t smem_u32 = (uint32_t)__cvta_generic_to_shared((void*)dsm);

    const int pxBase = blockIdx.x * 256;
    const int ocb = blockIdx.y;
    const int b = blockIdx.z;
    const int tid = threadIdx.x;
    const int lane = tid & 31;
    const int warp = tid >> 5;

    const int wm = warp >> 2;
    const int wn = warp & 3;
    const int px0 = wn * 64;
    const int tig = lane & 3;
    const int grp = lane >> 2;

    const float* xb = x + (size_t)b * C_IN * HWSZ + pxBase;
    const uint32_t* ws_base = wslab + (size_t)ocb * NC * (8 * 64);

    float acc[2][8][4];
    #pragma unroll
    for (int mf = 0; mf < 2; mf++)
        #pragma unroll
        for (int nf = 0; nf < 8; nf++)
            #pragma unroll
            for (int r = 0; r < 4; r++) acc[mf][nf][r] = 0.f;

    auto stage = [&](int buf, int cc) {
        const uint32_t xdst0 = smem_u32 + (buf ? X1_BUF_W * 4 : 0);
        const float* src = xb + (size_t)(cc * 8) * HWSZ;
        #pragma unroll
        for (int i = tid; i < 8 * 64; i += 256) {
            int ic = i >> 6;
            int piece = i & 63;
            cp_async16(xdst0 + (ic * 264 + piece * 4) * 4,
                       src + (size_t)ic * HWSZ + piece * 4);
        }
        const uint32_t wdst0 =
            smem_u32 + (2 * X1_BUF_W + (buf ? W1_BUF_W : 0)) * 4;
        const uint32_t* ws = ws_base + (size_t)cc * (8 * 64);
        if (tid < 128) {
            int row = tid >> 4;
            int piece = tid & 15;
            cp_async16(wdst0 + (row * 72 + piece * 4) * 4,
                       ws + row * 64 + piece * 4);
        }
    };

    auto compute = [&](int buf) {
        const uint32_t* pB = Xb[buf] + tig * 264 + px0 + grp;
        const uint32_t* pA = Wb[buf] + tig * 72 + wm * 32 + grp;
        uint32_t a[2][4];
        #pragma unroll
        for (int mf = 0; mf < 2; mf++) {
            const int base = mf * 16;
            a[mf][0] = pA[base];
            a[mf][1] = pA[base + 8];
            a[mf][2] = pA[base + 288];
            a[mf][3] = pA[base + 296];
        }
        #pragma unroll
        for (int nf = 0; nf < 8; nf++) {
            uint32_t b0 = tf32_of_bits(pB[nf * 8]);
            uint32_t b1 = tf32_of_bits(pB[1056 + nf * 8]);
            mma_tf32(acc[0][nf], a[0], b0, b1);
            mma_tf32(acc[1][nf], a[1], b0, b1);
        }
    };

    stage(0, 0);
    cp_commit();
    int buf = 0;
    for (int cc = 0; cc < NC; ++cc) {
        if (cc + 1 < NC) stage(buf ^ 1, cc + 1);
        cp_commit();
        if (cc + 1 < NC) cp_wait1(); else cp_wait0();
        __syncthreads();
        compute(buf);
        __syncthreads();
        buf ^= 1;
    }

    // epilogue: BN + ReLU -> NHWC fp16
    #pragma unroll
    for (int mf = 0; mf < 2; mf++) {
        #pragma unroll
        for (int rr = 0; rr < 2; rr++) {
            int oc = ocb * 64 + wm * 32 + mf * 16 + grp + rr * 8;
            float s = __ldg(&gg[oc]) * rsqrtf(__ldg(&vv[oc]) + EPSV);
            float t = (__ldg(&bb[oc]) - __ldg(&mm[oc])) * s + __ldg(&be[oc]);
            #pragma unroll
            for (int nf = 0; nf < 8; nf++) {
                float v0 = fmaxf(fmaf(acc[mf][nf][rr * 2 + 0], s, t), 0.f);
                float v1 = fmaxf(fmaf(acc[mf][nf][rr * 2 + 1], s, t), 0.f);
                int pxl = pxBase + px0 + nf * 8 + tig * 2;
                __half* dst = out + ((size_t)b * HWSZ + pxl) * C1 + oc;
                dst[0] = __float2half(v0);
                dst[C1] = __float2half(v1);
            }
        }
    }
}

// ---------------------------------------------------------------------------
// conv3x3 fp16 implicit GEMM, ldmatrix fragment loads.
// CTA: 256 px (2 output rows) x 64 oc. 8 warps: warp = m32 x n64.
// X smem: [4 rows][130 px][12 words]; W smem: [9 tap][64 oc][12 words].
// Row stride 48B -> ldmatrix phases hit all 32 banks (12k mod 32 distinct).
// MODE 0: out NHWC fp32 (C=128).  MODE 1: out NCHW fp32, ch offset 64.
// ---------------------------------------------------------------------------
#define XPXW 12
#define XROWW (130 * XPXW)
#define XBUFW (4 * XROWW)          // 6240
#define WBUFW (576 * XPXW)         // 6912
#define SMEMF16_WORDS (2 * XBUFW + 2 * WBUFW)
#define SMEMF16_BYTES (SMEMF16_WORDS * 4)

template <int CIN, int MODE>
__global__ __launch_bounds__(256, 2) void conv3x3_f16(
    const __half* __restrict__ in, const __half* __restrict__ wslab,
    const float* __restrict__ bb, const float* __restrict__ gg,
    const float* __restrict__ be, const float* __restrict__ mm,
    const float* __restrict__ vv, float* __restrict__ outp) {
    constexpr int NC = CIN / 16;
    extern __shared__ uint32_t dsm[];
    const uint32_t smem_u32 = (uint32_t)__cvta_generic_to_shared((void*)dsm);

    const int y0 = blockIdx.x * 2;
    const int ocb = blockIdx.y;
    const int b = blockIdx.z;
    const int tid = threadIdx.x;
    const int lane = tid & 31;
    const int warp = tid >> 5;
    const int row_out = warp >> 2;
    const int x0 = (warp & 3) * 32;
    const int grp = lane >> 2;
    const int tig = lane & 3;

    const __half* inb = in + (size_t)b * HWSZ * CIN;
    const __half* wsb = wslab + (size_t)ocb * ((size_t)NC * 9 * 64 * 16);

    // zero X halo regions once, then barrier before any cp.async can land
    for (int i = tid; i < 2 * XBUFW; i += 256) dsm[i] = 0;
    __syncthreads();

    float acc[2][8][4];
    #pragma unroll
    for (int mf = 0; mf < 2; mf++)
        #pragma unroll
        for (int nf = 0; nf < 8; nf++)
            #pragma unroll
            for (int r = 0; r < 4; r++) acc[mf][nf][r] = 0.f;

    // ---- per-lane ldmatrix base addresses (byte offsets, buf-relative) ----
    const int lg = lane >> 3;   // lane group 0..3 -> x4 tile slot
    const int r8 = lane & 7;
    // A tiles: reg0 rows+0 k-lo | reg1 rows+8 k-lo | reg2 rows+0 k-hi | reg3 rows+8 k-hi
    const int mA = ((lg & 1) << 3) + r8;
    const int pieceA = lg >> 1;
    uint32_t aRel[2];
    #pragma unroll
    for (int mf = 0; mf < 2; mf++)
        aRel[mf] = ((row_out * 130 + x0 + mf * 16 + mA) * XPXW + pieceA * 4) * 4;
    // B tiles: reg0 oc+0 k-lo | reg1 oc+0 k-hi | reg2 oc+8 k-lo | reg3 oc+8 k-hi
    const int ocB = ((lg >> 1) << 3) + r8;
    const int pieceB = lg & 1;
    uint32_t bRel[4];
    #pragma unroll
    for (int p = 0; p < 4; p++)
        bRel[p] = ((p * 16 + ocB) * XPXW + pieceB * 4) * 4;

    auto stage = [&](int buf, int cc) {
        const uint32_t xdst = smem_u32 + (buf ? XBUFW * 4 : 0);
        const __half* xs = inb + cc * 16;
        #pragma unroll
        for (int i = tid; i < 1024; i += 256) {
            int row = i >> 8;
            int r = i & 255;
            int px = r >> 1;
            int piece = r & 1;
            int gy = y0 - 1 + row;
            if ((unsigned)gy < (unsigned)HH)
                cp_async16(xdst + (((row * 130) + px + 1) * XPXW + piece * 4) * 4,
                           xs + ((size_t)gy * WWID + px) * CIN + piece * 8);
        }
        const uint32_t wdst = smem_u32 + (2 * XBUFW + (buf ? WBUFW : 0)) * 4;
        const __half* ws = wsb + (size_t)cc * (9 * 64 * 16);
        #pragma unroll
        for (int i = tid; i < 1152; i += 256) {
            int row = i >> 1;
            int piece = i & 1;
            cp_async16(wdst + (row * XPXW + piece * 4) * 4,
                       ws + row * 16 + piece * 8);
        }
    };

    auto compute = [&](int buf) {
        const uint32_t xo = smem_u32 + (buf ? XBUFW * 4u : 0u);
        const uint32_t wo = smem_u32 + (2 * XBUFW + (buf ? WBUFW : 0)) * 4u;
        #pragma unroll
        for (int tap = 0; tap < 9; ++tap) {
            const int ky = tap / 3;
            const int kx = tap - ky * 3;
            const uint32_t tA = (uint32_t)((ky * 130 + kx) * XPXW * 4);
            uint32_t a[2][4];
            ldsm_x4(a[0], xo + aRel[0] + tA);
            ldsm_x4(a[1], xo + aRel[1] + tA);
            const uint32_t tB = wo + (uint32_t)(tap * 64 * XPXW * 4);
            #pragma unroll
            for (int p = 0; p < 4; p++) {
                uint32_t bf[4];
                ldsm_x4(bf, tB + bRel[p]);
                mma_f16(acc[0][2 * p], a[0], bf[0], bf[1]);
                mma_f16(acc[1][2 * p], a[1], bf[0], bf[1]);
                mma_f16(acc[0][2 * p + 1], a[0], bf[2], bf[3]);
                mma_f16(acc[1][2 * p + 1], a[1], bf[2], bf[3]);
            }
        }
    };

    stage(0, 0);
    cp_commit();
    int buf = 0;
    for (int cc = 0; cc < NC; ++cc) {
        if (cc + 1 < NC) stage(buf ^ 1, cc + 1);
        cp_commit();
        if (cc + 1 < NC) cp_wait1(); else cp_wait0();
        __syncthreads();
        compute(buf);
        __syncthreads();
        buf ^= 1;
    }

    if (MODE == 0) {
        // NHWC fp32 output (c2 stays full precision for sobel cancellation)
        float* out = outp + (size_t)b * HWSZ * C2;
        #pragma unroll
        for (int nf = 0; nf < 8; nf++) {
            int oc = ocb * 64 + nf * 8 + 2 * tig;
            float s0 = __ldg(&gg[oc]) * rsqrtf(__ldg(&vv[oc]) + EPSV);
            float t0 = (__ldg(&bb[oc]) - __ldg(&mm[oc])) * s0 + __ldg(&be[oc]);
            float s1 = __ldg(&gg[oc + 1]) * rsqrtf(__ldg(&vv[oc + 1]) + EPSV);
            float t1 = (__ldg(&bb[oc + 1]) - __ldg(&mm[oc + 1])) * s1 +
                       __ldg(&be[oc + 1]);
            #pragma unroll
            for (int mf = 0; mf < 2; mf++)
                #pragma unroll
                for (int h = 0; h < 2; h++) {
                    int px = (y0 + row_out) * WWID + x0 + mf * 16 + grp + h * 8;
                    float2 v;
                    v.x = fmaxf(fmaf(acc[mf][nf][h * 2 + 0], s0, t0), 0.f);
                    v.y = fmaxf(fmaf(acc[mf][nf][h * 2 + 1], s1, t1), 0.f);
                    *(float2*)(out + (size_t)px * C2 + oc) = v;
                }
        }
    } else {
        // NCHW fp32 output at channel offset 64, smem transpose for coalescing
        float* Csm = (float*)dsm;  // [256 px][stride 65]
        #pragma unroll
        for (int nf = 0; nf < 8; nf++) {
            int ocL = nf * 8 + 2 * tig;
            float s0 = __ldg(&gg[ocL]) * rsqrtf(__ldg(&vv[ocL]) + EPSV);
            float t0 =
                (__ldg(&bb[ocL]) - __ldg(&mm[ocL])) * s0 + __ldg(&be[ocL]);
            float s1 = __ldg(&gg[ocL + 1]) * rsqrtf(__ldg(&vv[ocL + 1]) + EPSV);
            float t1 = (__ldg(&bb[ocL + 1]) - __ldg(&mm[ocL + 1])) * s1 +
                       __ldg(&be[ocL + 1]);
            #pragma unroll
            for (int mf = 0; mf < 2; mf++)
                #pragma unroll
                for (int h = 0; h < 2; h++) {
                    int pxL = row_out * 128 + x0 + mf * 16 + grp + h * 8;
                    Csm[pxL * 65 + ocL] =
                        fmaxf(fmaf(acc[mf][nf][h * 2 + 0], s0, t0), 0.f);
                    Csm[pxL * 65 + ocL + 1] =
                        fmaxf(fmaf(acc[mf][nf][h * 2 + 1], s1, t1), 0.f);
                }
        }
        __syncthreads();
        #pragma unroll
        for (int i = 0; i < 8; i++) {
            int ocL = warp * 8 + i;
            float* op =
                outp + ((size_t)(b * 128 + 64 + ocL)) * HWSZ + y0 * WWID;
            #pragma unroll
            for (int c = 0; c < 8; c++) {
                int pxL = c * 32 + lane;
                op[pxL] = Csm[pxL * 65 + ocL];
            }
        }
    }
}

// ---------------------------------------------------------------------------
// sobel depthwise: NHWC fp32 in -> NHWC fp16 out (8 channels / thread)
// kernel (correlation): [[2,4,4],[-2,0,2],[-4,-4,-2]]
// ---------------------------------------------------------------------------
__global__ __launch_bounds__(256) void sobel_nhwc(const float* __restrict__ in,
                                                  __half* __restrict__ out) {
    int idx = blockIdx.x * 256 + threadIdx.x;  // B*HW*16 threads
    int cg = idx & 15;
    int x = (idx >> 4) & 127;
    int y = (idx >> 11) & 127;
    int b = idx >> 18;
    const float* base = in + ((size_t)b * HWSZ + y * WWID + x) * C2 + cg * 8;

    float acc[8];
    #pragma unroll
    for (int k = 0; k < 8; k++) acc[k] = 0.f;

    auto add = [&](int dy, int dx, float c) {
        int yy = y + dy, xx = x + dx;
        if ((unsigned)yy < (unsigned)HH && (unsigned)xx < (unsigned)WWID) {
            const float* p = base + (dy * WWID + dx) * C2;
            float4 v0 = *(const float4*)p;
            float4 v1 = *(const float4*)(p + 4);
            acc[0] = fmaf(c, v0.x, acc[0]);
            acc[1] = fmaf(c, v0.y, acc[1]);
            acc[2] = fmaf(c, v0.z, acc[2]);
            acc[3] = fmaf(c, v0.w, acc[3]);
            acc[4] = fmaf(c, v1.x, acc[4]);
            acc[5] = fmaf(c, v1.y, acc[5]);
            acc[6] = fmaf(c, v1.z, acc[6]);
            acc[7] = fmaf(c, v1.w, acc[7]);
        }
    };
    add(-1, -1, 2.f);  add(-1, 0, 4.f);  add(-1, 1, 4.f);
    add(0, -1, -2.f);                    add(0, 1, 2.f);
    add(1, -1, -4.f);  add(1, 0, -4.f);  add(1, 1, -2.f);

    __half2 r[4];
    #pragma unroll
    for (int k = 0; k < 4; k++)
        r[k] = __floats2half2_rn(acc[2 * k], acc[2 * k + 1]);
    *(uint4*)(out + ((size_t)b * HWSZ + y * WWID + x) * C2 + cg * 8) =
        *(uint4*)r;
}

// ---------------------------------------------------------------------------
__global__ __launch_bounds__(256) void concat_copy(const float4* __restrict__ in,
                                                   float4* __restrict__ out) {
    int idx = blockIdx.x * 256 + threadIdx.x;
    int b = idx >> 18;
    int r = idx & 262143;
    out[(size_t)b * 524288 + r] = in[(size_t)b * 262144 + r];
}

// ---------------------------------------------------------------------------
extern "C" void kernel_launch(void* const* d_in, const int* in_sizes, int n_in,
                              void* d_out, int out_size) {
    const float* input = (const float*)d_in[0];
    const float* w1 = (const float*)d_in[1];
    const float* b1 = (const float*)d_in[2];
    const float* g1 = (const float*)d_in[3];
    const float* be1 = (const float*)d_in[4];
    const float* m1 = (const float*)d_in[5];
    const float* v1 = (const float*)d_in[6];
    const float* w2 = (const float*)d_in[7];
    const float* b2 = (const float*)d_in[8];
    const float* g2 = (const float*)d_in[9];
    const float* be2 = (const float*)d_in[10];
    const float* m2 = (const float*)d_in[11];
    const float* v2 = (const float*)d_in[12];
    const float* w3 = (const float*)d_in[13];
    const float* b3 = (const float*)d_in[14];
    const float* g3 = (const float*)d_in[15];
    const float* be3 = (const float*)d_in[16];
    const float* m3 = (const float*)d_in[17];
    const float* v3 = (const float*)d_in[18];
    float* out = (float*)d_out;

    __half *c1h, *edgeh, *w2h, *w3h;
    float* c2f;
    uint32_t* w1t;
    cudaGetSymbolAddress((void**)&c1h, g_c1h);
    cudaGetSymbolAddress((void**)&c2f, g_c2f);
    cudaGetSymbolAddress((void**)&edgeh, g_edgeh);
    cudaGetSymbolAddress((void**)&w2h, g_w2h);
    cudaGetSymbolAddress((void**)&w3h, g_w3h);
    cudaGetSymbolAddress((void**)&w1t, g_w1t);

    static int attr_done = 0;
    if (!attr_done) {
        cudaFuncSetAttribute(conv1x1_mma_pipe,
                             cudaFuncAttributeMaxDynamicSharedMemorySize,
                             SMEM1X1_BYTES);
        cudaFuncSetAttribute(conv3x3_f16<C1, 0>,
                             cudaFuncAttributeMaxDynamicSharedMemorySize,
                             SMEMF16_BYTES);
        cudaFuncSetAttribute(conv3x3_f16<C2, 1>,
                             cudaFuncAttributeMaxDynamicSharedMemorySize,
                             SMEMF16_BYTES);
        attr_done = 1;
    }

    // weight prep
    prep_w1x1<<<(C1 * C_IN + 255) / 256, 256>>>(w1, w1t);
    prep_w3x3_h<<<(C2 * C1 * 9 + 255) / 256, 256>>>(w2, w2h, C2, C1);
    prep_w3x3_h<<<(C3 * C2 * 9 + 255) / 256, 256>>>(w3, w3h, C3, C2);

    // conv1: 1x1 64->256 (TF32) -> NHWC fp16
    conv1x1_mma_pipe<<<dim3(HWSZ / 256, C1 / 64, BATCH), 256, SMEM1X1_BYTES>>>(
        input, w1t, b1, g1, be1, m1, v1, c1h);

    // conv2: 3x3 256->128 (FP16 mma, ldmatrix) -> NHWC fp32
    conv3x3_f16<C1, 0><<<dim3(HH / 2, 2, BATCH), 256, SMEMF16_BYTES>>>(
        c1h, w2h, b2, g2, be2, m2, v2, c2f);

    // sobel depthwise (fp32 in -> fp16 out)
    sobel_nhwc<<<BATCH * HWSZ * (C2 / 8) / 256, 256>>>(c2f, edgeh);

    // conv3: 3x3 128->64 (FP16 mma, ldmatrix) -> out[:,64:128] NCHW fp32
    conv3x3_f16<C2, 1><<<dim3(HH / 2, 1, BATCH), 256, SMEMF16_BYTES>>>(
        edgeh, w3h, b3, g3, be3, m3, v3, out);

    // concat: out[:,0:64] = input
    concat_copy<<<BATCH * (C_IN * HWSZ / 4) / 256, 256>>>(
        (const float4*)input, (float4*)out);
}

// round 15
// speedup vs baseline: 1.0026x; 1.0002x over previous
#include <cuda_runtime.h>
#include <cuda_fp16.h>
#include <cstdint>

// ---------------------------------------------------------------------------
//   input:  [16, 64, 128, 128]  fp32 NCHW
//   conv1:  1x1, 64 -> 256, BN+ReLU  (TF32 mma)       -> c1  NHWC fp16
//   conv2:  3x3 pad1, 256 -> 128, BN+ReLU (FP16 mma)  -> c2  NHWC fp32
//   sobel:  depthwise 3x3 pad1 (summed kernel)        -> edge NHWC fp16
//   conv3:  3x3 pad1, 128 -> 64, BN+ReLU (FP16 mma)   -> out[:,64:128] NCHW f32
//   concat: out[:,0:64] = input
//
// R8 -> R9: conv3x3 fragment loads via ldmatrix.x4 (2 for A, 4 for B per tap)
// instead of 24 scalar LDS. Same fragments, bit-identical math.
// ---------------------------------------------------------------------------

#define BATCH 16
#define HH 128
#define WWID 128
#define HWSZ (HH * WWID)
#define C_IN 64
#define C1 256
#define C2 128
#define C3 64
#define EPSV 1e-5f

__device__ __align__(16) __half g_c1h[(size_t)BATCH * HWSZ * C1];    // 128 MB
__device__ __align__(16) float g_c2f[(size_t)BATCH * HWSZ * C2];     // 128 MB
__device__ __align__(16) __half g_edgeh[(size_t)BATCH * HWSZ * C2];  // 64 MB
__device__ __align__(16) __half g_w2h[2 * 16 * 9 * 64 * 16];  // [ocb][cc][tap][oc64][ic16]
__device__ __align__(16) __half g_w3h[1 * 8 * 9 * 64 * 16];
__device__ uint32_t g_w1t[4 * 8 * 8 * 64];                    // conv1 tf32 slab

// ---------------------------------------------------------------------------
// helpers
// ---------------------------------------------------------------------------
__device__ __forceinline__ uint32_t f2tf32(float x) {
    uint32_t r;
    asm("cvt.rna.tf32.f32 %0, %1;" : "=r"(r) : "f"(x));
    return r;
}
__device__ __forceinline__ uint32_t tf32_of_bits(uint32_t b) {
    return f2tf32(__uint_as_float(b));
}

__device__ __forceinline__ void mma_tf32(float c[4], const uint32_t a[4],
                                         uint32_t b0, uint32_t b1) {
    asm volatile(
        "mma.sync.aligned.m16n8k8.row.col.f32.tf32.tf32.f32 "
        "{%0,%1,%2,%3}, {%4,%5,%6,%7}, {%8,%9}, {%0,%1,%2,%3};"
        : "+f"(c[0]), "+f"(c[1]), "+f"(c[2]), "+f"(c[3])
        : "r"(a[0]), "r"(a[1]), "r"(a[2]), "r"(a[3]), "r"(b0), "r"(b1));
}

__device__ __forceinline__ void mma_f16(float c[4], const uint32_t a[4],
                                        uint32_t b0, uint32_t b1) {
    asm volatile(
        "mma.sync.aligned.m16n8k16.row.col.f32.f16.f16.f32 "
        "{%0,%1,%2,%3}, {%4,%5,%6,%7}, {%8,%9}, {%0,%1,%2,%3};"
        : "+f"(c[0]), "+f"(c[1]), "+f"(c[2]), "+f"(c[3])
        : "r"(a[0]), "r"(a[1]), "r"(a[2]), "r"(a[3]), "r"(b0), "r"(b1));
}

__device__ __forceinline__ void ldsm_x4(uint32_t r[4], uint32_t addr) {
    asm volatile(
        "ldmatrix.sync.aligned.m8n8.x4.shared.b16 {%0,%1,%2,%3}, [%4];"
        : "=r"(r[0]), "=r"(r[1]), "=r"(r[2]), "=r"(r[3])
        : "r"(addr));
}

__device__ __forceinline__ void cp_async16(uint32_t dst, const void* src) {
    asm volatile("cp.async.cg.shared.global [%0], [%1], 16;\n" ::"r"(dst),
                 "l"(src));
}
__device__ __forceinline__ void cp_commit() {
    asm volatile("cp.async.commit_group;\n" ::: "memory");
}
__device__ __forceinline__ void cp_wait1() {
    asm volatile("cp.async.wait_group 1;\n" ::: "memory");
}
__device__ __forceinline__ void cp_wait0() {
    asm volatile("cp.async.wait_group 0;\n" ::: "memory");
}

// ---------------------------------------------------------------------------
// weight prep
// ---------------------------------------------------------------------------
__global__ void prep_w3x3_h(const float* __restrict__ w,
                            __half* __restrict__ o, int OC, int CIN) {
    int t = blockIdx.x * 256 + threadIdx.x;
    int total = OC * CIN * 9;
    if (t >= total) return;
    int oc = t / (CIN * 9);
    int r = t - oc * (CIN * 9);
    int ic = r / 9;
    int tap = r - ic * 9;
    int ocb = oc >> 6, oc64 = oc & 63;
    int cc = ic >> 4, icr = ic & 15;
    int NC = CIN / 16;
    o[((((size_t)ocb * NC + cc) * 9 + tap) * 64 + oc64) * 16 + icr] =
        __float2half(w[t]);
}

__global__ void prep_w1x1(const float* __restrict__ w,
                          uint32_t* __restrict__ o) {
    int t = blockIdx.x * 256 + threadIdx.x;
    if (t >= C1 * C_IN) return;
    int oc = t / C_IN;
    int ic = t - oc * C_IN;
    int ocb = oc >> 6, oc64 = oc & 63;
    int cc = ic >> 3, icr = ic & 7;
    o[(((size_t)ocb * 8 + cc) * 8 + icr) * 64 + oc64] = f2tf32(w[t]);
}

// ---------------------------------------------------------------------------
// conv1: 1x1 64->256, TF32 mma, cp.async pipelined -> NHWC fp16
// ---------------------------------------------------------------------------
#define X1_BUF_W 2112  // 8*264
#define W1_BUF_W 576   // 8*72
#define SMEM1X1_BYTES ((2 * X1_BUF_W + 2 * W1_BUF_W) * 4)

__global__ __launch_bounds__(256, 2) void conv1x1_mma_pipe(
    const float* __restrict__ x, const uint32_t* __restrict__ wslab,
    const float* __restrict__ bb, const float* __restrict__ gg,
    const float* __restrict__ be, const float* __restrict__ mm,
    const float* __restrict__ vv, __half* __restrict__ out) {
    constexpr int NC = 8;
    extern __shared__ uint32_t dsm[];
    uint32_t* Xb[2] = {dsm, dsm + X1_BUF_W};
    uint32_t* Wb[2] = {dsm + 2 * X1_BUF_W, dsm + 2 * X1_BUF_W + W1_BUF_W};
    const uint32_t smem_u32 = (uint32_t)__cvta_generic_to_shared((void*)dsm);

    const int pxBase = blockIdx.x * 256;
    const int ocb = blockIdx.y;
    const int b = blockIdx.z;
    const int tid = threadIdx.x;
    const int lane = tid & 31;
    const int warp = tid >> 5;

    const int wm = warp >> 2;
    const int wn = warp & 3;
    const int px0 = wn * 64;
    const int tig = lane & 3;
    const int grp = lane >> 2;

    const float* xb = x + (size_t)b * C_IN * HWSZ + pxBase;
    const uint32_t* ws_base = wslab + (size_t)ocb * NC * (8 * 64);

    float acc[2][8][4];
    #pragma unroll
    for (int mf = 0; mf < 2; mf++)
        #pragma unroll
        for (int nf = 0; nf < 8; nf++)
            #pragma unroll
            for (int r = 0; r < 4; r++) acc[mf][nf][r] = 0.f;

    auto stage = [&](int buf, int cc) {
        const uint32_t xdst0 = smem_u32 + (buf ? X1_BUF_W * 4 : 0);
        const float* src = xb + (size_t)(cc * 8) * HWSZ;
        #pragma unroll
        for (int i = tid; i < 8 * 64; i += 256) {
            int ic = i >> 6;
            int piece = i & 63;
            cp_async16(xdst0 + (ic * 264 + piece * 4) * 4,
                       src + (size_t)ic * HWSZ + piece * 4);
        }
        const uint32_t wdst0 =
            smem_u32 + (2 * X1_BUF_W + (buf ? W1_BUF_W : 0)) * 4;
        const uint32_t* ws = ws_base + (size_t)cc * (8 * 64);
        if (tid < 128) {
            int row = tid >> 4;
            int piece = tid & 15;
            cp_async16(wdst0 + (row * 72 + piece * 4) * 4,
                       ws + row * 64 + piece * 4);
        }
    };

    auto compute = [&](int buf) {
        const uint32_t* pB = Xb[buf] + tig * 264 + px0 + grp;
        const uint32_t* pA = Wb[buf] + tig * 72 + wm * 32 + grp;
        uint32_t a[2][4];
        #pragma unroll
        for (int mf = 0; mf < 2; mf++) {
            const int base = mf * 16;
            a[mf][0] = pA[base];
            a[mf][1] = pA[base + 8];
            a[mf][2] = pA[base + 288];
            a[mf][3] = pA[base + 296];
        }
        #pragma unroll
        for (int nf = 0; nf < 8; nf++) {
            uint32_t b0 = tf32_of_bits(pB[nf * 8]);
            uint32_t b1 = tf32_of_bits(pB[1056 + nf * 8]);
            mma_tf32(acc[0][nf], a[0], b0, b1);
            mma_tf32(acc[1][nf], a[1], b0, b1);
        }
    };

    stage(0, 0);
    cp_commit();
    int buf = 0;
    for (int cc = 0; cc < NC; ++cc) {
        if (cc + 1 < NC) stage(buf ^ 1, cc + 1);
        cp_commit();
        if (cc + 1 < NC) cp_wait1(); else cp_wait0();
        __syncthreads();
        compute(buf);
        __syncthreads();
        buf ^= 1;
    }

    // epilogue: BN + ReLU -> NHWC fp16
    #pragma unroll
    for (int mf = 0; mf < 2; mf++) {
        #pragma unroll
        for (int rr = 0; rr < 2; rr++) {
            int oc = ocb * 64 + wm * 32 + mf * 16 + grp + rr * 8;
            float s = __ldg(&gg[oc]) * rsqrtf(__ldg(&vv[oc]) + EPSV);
            float t = (__ldg(&bb[oc]) - __ldg(&mm[oc])) * s + __ldg(&be[oc]);
            #pragma unroll
            for (int nf = 0; nf < 8; nf++) {
                float v0 = fmaxf(fmaf(acc[mf][nf][rr * 2 + 0], s, t), 0.f);
                float v1 = fmaxf(fmaf(acc[mf][nf][rr * 2 + 1], s, t), 0.f);
                int pxl = pxBase + px0 + nf * 8 + tig * 2;
                __half* dst = out + ((size_t)b * HWSZ + pxl) * C1 + oc;
                dst[0] = __float2half(v0);
                dst[C1] = __float2half(v1);
            }
        }
    }
}

// ---------------------------------------------------------------------------
// conv3x3 fp16 implicit GEMM, ldmatrix fragment loads.
// CTA: 256 px (2 output rows) x 64 oc. 8 warps: warp = m32 x n64.
// X smem: [4 rows][130 px][12 words]; W smem: [9 tap][64 oc][12 words].
// Row stride 48B -> ldmatrix phases hit all 32 banks (12k mod 32 distinct).
// MODE 0: out NHWC fp32 (C=128).  MODE 1: out NCHW fp32, ch offset 64.
// ---------------------------------------------------------------------------
#define XPXW 12
#define XROWW (130 * XPXW)
#define XBUFW (4 * XROWW)          // 6240
#define WBUFW (576 * XPXW)         // 6912
#define SMEMF16_WORDS (2 * XBUFW + 2 * WBUFW)
#define SMEMF16_BYTES (SMEMF16_WORDS * 4)

template <int CIN, int MODE>
__global__ __launch_bounds__(256, 2) void conv3x3_f16(
    const __half* __restrict__ in, const __half* __restrict__ wslab,
    const float* __restrict__ bb, const float* __restrict__ gg,
    const float* __restrict__ be, const float* __restrict__ mm,
    const float* __restrict__ vv, float* __restrict__ outp) {
    constexpr int NC = CIN / 16;
    extern __shared__ uint32_t dsm[];
    const uint32_t smem_u32 = (uint32_t)__cvta_generic_to_shared((void*)dsm);

    const int y0 = blockIdx.x * 2;
    const int ocb = blockIdx.y;
    const int b = blockIdx.z;
    const int tid = threadIdx.x;
    const int lane = tid & 31;
    const int warp = tid >> 5;
    const int row_out = warp >> 2;
    const int x0 = (warp & 3) * 32;
    const int grp = lane >> 2;
    const int tig = lane & 3;

    const __half* inb = in + (size_t)b * HWSZ * CIN;
    const __half* wsb = wslab + (size_t)ocb * ((size_t)NC * 9 * 64 * 16);

    // zero X halo regions once, then barrier before any cp.async can land
    for (int i = tid; i < 2 * XBUFW; i += 256) dsm[i] = 0;
    __syncthreads();

    float acc[2][8][4];
    #pragma unroll
    for (int mf = 0; mf < 2; mf++)
        #pragma unroll
        for (int nf = 0; nf < 8; nf++)
            #pragma unroll
            for (int r = 0; r < 4; r++) acc[mf][nf][r] = 0.f;

    // ---- per-lane ldmatrix base addresses (byte offsets, buf-relative) ----
    const int lg = lane >> 3;   // lane group 0..3 -> x4 tile slot
    const int r8 = lane & 7;
    // A tiles: reg0 rows+0 k-lo | reg1 rows+8 k-lo | reg2 rows+0 k-hi | reg3 rows+8 k-hi
    const int mA = ((lg & 1) << 3) + r8;
    const int pieceA = lg >> 1;
    uint32_t aRel[2];
    #pragma unroll
    for (int mf = 0; mf < 2; mf++)
        aRel[mf] = ((row_out * 130 + x0 + mf * 16 + mA) * XPXW + pieceA * 4) * 4;
    // B tiles: reg0 oc+0 k-lo | reg1 oc+0 k-hi | reg2 oc+8 k-lo | reg3 oc+8 k-hi
    const int ocB = ((lg >> 1) << 3) + r8;
    const int pieceB = lg & 1;
    uint32_t bRel[4];
    #pragma unroll
    for (int p = 0; p < 4; p++)
        bRel[p] = ((p * 16 + ocB) * XPXW + pieceB * 4) * 4;

    auto stage = [&](int buf, int cc) {
        const uint32_t xdst = smem_u32 + (buf ? XBUFW * 4 : 0);
        const __half* xs = inb + cc * 16;
        #pragma unroll
        for (int i = tid; i < 1024; i += 256) {
            int row = i >> 8;
            int r = i & 255;
            int px = r >> 1;
            int piece = r & 1;
            int gy = y0 - 1 + row;
            if ((unsigned)gy < (unsigned)HH)
                cp_async16(xdst + (((row * 130) + px + 1) * XPXW + piece * 4) * 4,
                           xs + ((size_t)gy * WWID + px) * CIN + piece * 8);
        }
        const uint32_t wdst = smem_u32 + (2 * XBUFW + (buf ? WBUFW : 0)) * 4;
        const __half* ws = wsb + (size_t)cc * (9 * 64 * 16);
        #pragma unroll
        for (int i = tid; i < 1152; i += 256) {
            int row = i >> 1;
            int piece = i & 1;
            cp_async16(wdst + (row * XPXW + piece * 4) * 4,
                       ws + row * 16 + piece * 8);
        }
    };

    auto compute = [&](int buf) {
        const uint32_t xo = smem_u32 + (buf ? XBUFW * 4u : 0u);
        const uint32_t wo = smem_u32 + (2 * XBUFW + (buf ? WBUFW : 0)) * 4u;
        #pragma unroll
        for (int tap = 0; tap < 9; ++tap) {
            const int ky = tap / 3;
            const int kx = tap - ky * 3;
            const uint32_t tA = (uint32_t)((ky * 130 + kx) * XPXW * 4);
            uint32_t a[2][4];
            ldsm_x4(a[0], xo + aRel[0] + tA);
            ldsm_x4(a[1], xo + aRel[1] + tA);
            const uint32_t tB = wo + (uint32_t)(tap * 64 * XPXW * 4);
            #pragma unroll
            for (int p = 0; p < 4; p++) {
                uint32_t bf[4];
                ldsm_x4(bf, tB + bRel[p]);
                mma_f16(acc[0][2 * p], a[0], bf[0], bf[1]);
                mma_f16(acc[1][2 * p], a[1], bf[0], bf[1]);
                mma_f16(acc[0][2 * p + 1], a[0], bf[2], bf[3]);
                mma_f16(acc[1][2 * p + 1], a[1], bf[2], bf[3]);
            }
        }
    };

    stage(0, 0);
    cp_commit();
    int buf = 0;
    for (int cc = 0; cc < NC; ++cc) {
        if (cc + 1 < NC) stage(buf ^ 1, cc + 1);
        cp_commit();
        if (cc + 1 < NC) cp_wait1(); else cp_wait0();
        __syncthreads();
        compute(buf);
        __syncthreads();
        buf ^= 1;
    }

    if (MODE == 0) {
        // NHWC fp32 output (c2 stays full precision for sobel cancellation)
        float* out = outp + (size_t)b * HWSZ * C2;
        #pragma unroll
        for (int nf = 0; nf < 8; nf++) {
            int oc = ocb * 64 + nf * 8 + 2 * tig;
            float s0 = __ldg(&gg[oc]) * rsqrtf(__ldg(&vv[oc]) + EPSV);
            float t0 = (__ldg(&bb[oc]) - __ldg(&mm[oc])) * s0 + __ldg(&be[oc]);
            float s1 = __ldg(&gg[oc + 1]) * rsqrtf(__ldg(&vv[oc + 1]) + EPSV);
            float t1 = (__ldg(&bb[oc + 1]) - __ldg(&mm[oc + 1])) * s1 +
                       __ldg(&be[oc + 1]);
            #pragma unroll
            for (int mf = 0; mf < 2; mf++)
                #pragma unroll
                for (int h = 0; h < 2; h++) {
                    int px = (y0 + row_out) * WWID + x0 + mf * 16 + grp + h * 8;
                    float2 v;
                    v.x = fmaxf(fmaf(acc[mf][nf][h * 2 + 0], s0, t0), 0.f);
                    v.y = fmaxf(fmaf(acc[mf][nf][h * 2 + 1], s1, t1), 0.f);
                    *(float2*)(out + (size_t)px * C2 + oc) = v;
                }
        }
    } else {
        // NCHW fp32 output at channel offset 64, smem transpose for coalescing
        float* Csm = (float*)dsm;  // [256 px][stride 65]
        #pragma unroll
        for (int nf = 0; nf < 8; nf++) {
            int ocL = nf * 8 + 2 * tig;
            float s0 = __ldg(&gg[ocL]) * rsqrtf(__ldg(&vv[ocL]) + EPSV);
            float t0 =
                (__ldg(&bb[ocL]) - __ldg(&mm[ocL])) * s0 + __ldg(&be[ocL]);
            float s1 = __ldg(&gg[ocL + 1]) * rsqrtf(__ldg(&vv[ocL + 1]) + EPSV);
            float t1 = (__ldg(&bb[ocL + 1]) - __ldg(&mm[ocL + 1])) * s1 +
                       __ldg(&be[ocL + 1]);
            #pragma unroll
            for (int mf = 0; mf < 2; mf++)
                #pragma unroll
                for (int h = 0; h < 2; h++) {
                    int pxL = row_out * 128 + x0 + mf * 16 + grp + h * 8;
                    Csm[pxL * 65 + ocL] =
                        fmaxf(fmaf(acc[mf][nf][h * 2 + 0], s0, t0), 0.f);
                    Csm[pxL * 65 + ocL + 1] =
                        fmaxf(fmaf(acc[mf][nf][h * 2 + 1], s1, t1), 0.f);
                }
        }
        __syncthreads();
        #pragma unroll
        for (int i = 0; i < 8; i++) {
            int ocL = warp * 8 + i;
            float* op =
                outp + ((size_t)(b * 128 + 64 + ocL)) * HWSZ + y0 * WWID;
            #pragma unroll
            for (int c = 0; c < 8; c++) {
                int pxL = c * 32 + lane;
                op[pxL] = Csm[pxL * 65 + ocL];
            }
        }
    }
}

// ---------------------------------------------------------------------------
// sobel depthwise: NHWC fp32 in -> NHWC fp16 out (8 channels / thread)
// kernel (correlation): [[2,4,4],[-2,0,2],[-4,-4,-2]]
// ---------------------------------------------------------------------------
__global__ __launch_bounds__(256) void sobel_nhwc(const float* __restrict__ in,
                                                  __half* __restrict__ out) {
    int idx = blockIdx.x * 256 + threadIdx.x;  // B*HW*16 threads
    int cg = idx & 15;
    int x = (idx >> 4) & 127;
    int y = (idx >> 11) & 127;
    int b = idx >> 18;
    const float* base = in + ((size_t)b * HWSZ + y * WWID + x) * C2 + cg * 8;

    float acc[8];
    #pragma unroll
    for (int k = 0; k < 8; k++) acc[k] = 0.f;

    auto add = [&](int dy, int dx, float c) {
        int yy = y + dy, xx = x + dx;
        if ((unsigned)yy < (unsigned)HH && (unsigned)xx < (unsigned)WWID) {
            const float* p = base + (dy * WWID + dx) * C2;
            float4 v0 = *(const float4*)p;
            float4 v1 = *(const float4*)(p + 4);
            acc[0] = fmaf(c, v0.x, acc[0]);
            acc[1] = fmaf(c, v0.y, acc[1]);
            acc[2] = fmaf(c, v0.z, acc[2]);
            acc[3] = fmaf(c, v0.w, acc[3]);
            acc[4] = fmaf(c, v1.x, acc[4]);
            acc[5] = fmaf(c, v1.y, acc[5]);
            acc[6] = fmaf(c, v1.z, acc[6]);
            acc[7] = fmaf(c, v1.w, acc[7]);
        }
    };
    add(-1, -1, 2.f);  add(-1, 0, 4.f);  add(-1, 1, 4.f);
    add(0, -1, -2.f);                    add(0, 1, 2.f);
    add(1, -1, -4.f);  add(1, 0, -4.f);  add(1, 1, -2.f);

    __half2 r[4];
    #pragma unroll
    for (int k = 0; k < 4; k++)
        r[k] = __floats2half2_rn(acc[2 * k], acc[2 * k + 1]);
    *(uint4*)(out + ((size_t)b * HWSZ + y * WWID + x) * C2 + cg * 8) =
        *(uint4*)r;
}

// ---------------------------------------------------------------------------
__global__ __launch_bounds__(256) void concat_copy(const float4* __restrict__ in,
                                                   float4* __restrict__ out) {
    int idx = blockIdx.x * 256 + threadIdx.x;
    int b = idx >> 18;
    int r = idx & 262143;
    out[(size_t)b * 524288 + r] = in[(size_t)b * 262144 + r];
}

// ---------------------------------------------------------------------------
extern "C" void kernel_launch(void* const* d_in, const int* in_sizes, int n_in,
                              void* d_out, int out_size) {
    const float* input = (const float*)d_in[0];
    const float* w1 = (const float*)d_in[1];
    const float* b1 = (const float*)d_in[2];
    const float* g1 = (const float*)d_in[3];
    const float* be1 = (const float*)d_in[4];
    const float* m1 = (const float*)d_in[5];
    const float* v1 = (const float*)d_in[6];
    const float* w2 = (const float*)d_in[7];
    const float* b2 = (const float*)d_in[8];
    const float* g2 = (const float*)d_in[9];
    const float* be2 = (const float*)d_in[10];
    const float* m2 = (const float*)d_in[11];
    const float* v2 = (const float*)d_in[12];
    const float* w3 = (const float*)d_in[13];
    const float* b3 = (const float*)d_in[14];
    const float* g3 = (const float*)d_in[15];
    const float* be3 = (const float*)d_in[16];
    const float* m3 = (const float*)d_in[17];
    const float* v3 = (const float*)d_in[18];
    float* out = (float*)d_out;

    __half *c1h, *edgeh, *w2h, *w3h;
    float* c2f;
    uint32_t* w1t;
    cudaGetSymbolAddress((void**)&c1h, g_c1h);
    cudaGetSymbolAddress((void**)&c2f, g_c2f);
    cudaGetSymbolAddress((void**)&edgeh, g_edgeh);
    cudaGetSymbolAddress((void**)&w2h, g_w2h);
    cudaGetSymbolAddress((void**)&w3h, g_w3h);
    cudaGetSymbolAddress((void**)&w1t, g_w1t);

    static int attr_done = 0;
    if (!attr_done) {
        cudaFuncSetAttribute(conv1x1_mma_pipe,
                             cudaFuncAttributeMaxDynamicSharedMemorySize,
                             SMEM1X1_BYTES);
        cudaFuncSetAttribute(conv3x3_f16<C1, 0>,
                             cudaFuncAttributeMaxDynamicSharedMemorySize,
                             SMEMF16_BYTES);
        cudaFuncSetAttribute(conv3x3_f16<C2, 1>,
                             cudaFuncAttributeMaxDynamicSharedMemorySize,
                             SMEMF16_BYTES);
        attr_done = 1;
    }

    // weight prep
    prep_w1x1<<<(C1 * C_IN + 255) / 256, 256>>>(w1, w1t);
    prep_w3x3_h<<<(C2 * C1 * 9 + 255) / 256, 256>>>(w2, w2h, C2, C1);
    prep_w3x3_h<<<(C3 * C2 * 9 + 255) / 256, 256>>>(w3, w3h, C3, C2);

    // conv1: 1x1 64->256 (TF32) -> NHWC fp16
    conv1x1_mma_pipe<<<dim3(HWSZ / 256, C1 / 64, BATCH), 256, SMEM1X1_BYTES>>>(
        input, w1t, b1, g1, be1, m1, v1, c1h);

    // conv2: 3x3 256->128 (FP16 mma, ldmatrix) -> NHWC fp32
    conv3x3_f16<C1, 0><<<dim3(HH / 2, 2, BATCH), 256, SMEMF16_BYTES>>>(
        c1h, w2h, b2, g2, be2, m2, v2, c2f);

    // sobel depthwise (fp32 in -> fp16 out)
    sobel_nhwc<<<BATCH * HWSZ * (C2 / 8) / 256, 256>>>(c2f, edgeh);

    // conv3: 3x3 128->64 (FP16 mma, ldmatrix) -> out[:,64:128] NCHW fp32
    conv3x3_f16<C2, 1><<<dim3(HH / 2, 1, BATCH), 256, SMEMF16_BYTES>>>(
        edgeh, w3h, b3, g3, be3, m3, v3, out);

    // concat: out[:,0:64] = input
    concat_copy<<<BATCH * (C_IN * HWSZ / 4) / 256, 256>>>(
        (const float4*)input, (float4*)out);
}